// round 2
// baseline (speedup 1.0000x reference)
#include <cuda_runtime.h>
#include <cuda_bf16.h>
#include <cstdint>

// Problem constants (B=2, S=2048, D=512, K=64)
#define PB 2
#define PS 2048
#define PD 512
#define PK 64

// Scratch (device globals — no allocation allowed)
__device__ float g_h[PB * PS * PD];      // 8 MB
__device__ float g_fused[PB * PS * PD];  // 8 MB
__device__ float g_w[PS * PK];           // 512 KB

// ---------------------------------------------------------------------------
// GEMM (NT): C[m,n] = sum_k A[m,k] * W[n,k]  (both row-major, K contiguous)
// Optional epilogue: + bias[n] + resid[m*N+n]
// BM=128, BN=64, BK=16, 256 threads, each thread computes 8x4 fragment.
// ---------------------------------------------------------------------------
#define BM 128
#define BN 64
#define BK 16
#define TM 8
#define TN 4

template <bool EPI>
__global__ __launch_bounds__(256)
void gemm_nt_kernel(const float* __restrict__ A, const float* __restrict__ W,
                    float* __restrict__ C,
                    const float* __restrict__ bias, const float* __restrict__ resid,
                    int M, int N, int Kdim)
{
    __shared__ __align__(16) float As[BK][BM];
    __shared__ __align__(16) float Bs[BK][BN];

    const int tid = threadIdx.x;
    const int blockN = blockIdx.x * BN;
    const int blockM = blockIdx.y * BM;

    const int tm0 = (tid / 16) * TM;   // 0..120
    const int tn0 = (tid % 16) * TN;   // 0..60

    float acc[TM][TN];
#pragma unroll
    for (int i = 0; i < TM; i++)
#pragma unroll
        for (int j = 0; j < TN; j++) acc[i][j] = 0.0f;

    for (int kt = 0; kt < Kdim; kt += BK) {
        // Load A tile: BM x BK = 2048 floats = 512 float4; 2 per thread
#pragma unroll
        for (int j = 0; j < 2; j++) {
            int idx = tid + j * 256;
            int row = idx >> 2;            // 0..127
            int c4  = (idx & 3) * 4;       // 0,4,8,12
            float4 v = *(const float4*)&A[(size_t)(blockM + row) * Kdim + kt + c4];
            As[c4 + 0][row] = v.x;
            As[c4 + 1][row] = v.y;
            As[c4 + 2][row] = v.z;
            As[c4 + 3][row] = v.w;
        }
        // Load W tile: BN x BK = 1024 floats = 256 float4; 1 per thread
        {
            int idx = tid;
            int row = idx >> 2;            // 0..63
            int c4  = (idx & 3) * 4;
            float4 v = *(const float4*)&W[(size_t)(blockN + row) * Kdim + kt + c4];
            Bs[c4 + 0][row] = v.x;
            Bs[c4 + 1][row] = v.y;
            Bs[c4 + 2][row] = v.z;
            Bs[c4 + 3][row] = v.w;
        }
        __syncthreads();

#pragma unroll
        for (int k = 0; k < BK; k++) {
            float a[TM];
            float4 a0 = *(const float4*)&As[k][tm0];
            float4 a1 = *(const float4*)&As[k][tm0 + 4];
            a[0] = a0.x; a[1] = a0.y; a[2] = a0.z; a[3] = a0.w;
            a[4] = a1.x; a[5] = a1.y; a[6] = a1.z; a[7] = a1.w;
            float4 b4 = *(const float4*)&Bs[k][tn0];
            float b[TN] = {b4.x, b4.y, b4.z, b4.w};
#pragma unroll
            for (int i = 0; i < TM; i++)
#pragma unroll
                for (int j = 0; j < TN; j++)
                    acc[i][j] = fmaf(a[i], b[j], acc[i][j]);
        }
        __syncthreads();
    }

    // Epilogue / store
#pragma unroll
    for (int i = 0; i < TM; i++) {
        size_t rowoff = (size_t)(blockM + tm0 + i) * N + blockN + tn0;
        float4 r;
        r.x = acc[i][0]; r.y = acc[i][1]; r.z = acc[i][2]; r.w = acc[i][3];
        if (EPI) {
            float4 bb = *(const float4*)&bias[blockN + tn0];
            float4 xx = *(const float4*)&resid[rowoff];
            r.x += bb.x + xx.x;
            r.y += bb.y + xx.y;
            r.z += bb.z + xx.z;
            r.w += bb.w + xx.w;
        }
        *(float4*)&C[rowoff] = r;
    }
}

// ---------------------------------------------------------------------------
// Softmax over gathered distances: w[s,k] = softmax_k(-distances[s, routes[s,k]])
// One block per s, 64 threads.
// ---------------------------------------------------------------------------
__global__ __launch_bounds__(PK)
void softmax_kernel(const int* __restrict__ routes, const float* __restrict__ dist,
                    float* __restrict__ w)
{
    const int s = blockIdx.x;
    const int t = threadIdx.x;
    __shared__ float red[PK];

    int r = routes[s * PK + t];
    float v = -dist[(size_t)s * PS + r];

    red[t] = v;
    __syncthreads();
#pragma unroll
    for (int off = PK / 2; off > 0; off >>= 1) {
        if (t < off) red[t] = fmaxf(red[t], red[t + off]);
        __syncthreads();
    }
    float m = red[0];
    __syncthreads();

    float e = __expf(v - m);
    red[t] = e;
    __syncthreads();
#pragma unroll
    for (int off = PK / 2; off > 0; off >>= 1) {
        if (t < off) red[t] += red[t + off];
        __syncthreads();
    }
    float inv = 1.0f / red[0];

    w[s * PK + t] = e * inv;
}

// ---------------------------------------------------------------------------
// Gather-fuse: fused[b,s,:] = sum_k w[s,k] * h[b, routes[s,k], :]
// One block per (s,b), 128 threads, each owns one float4 column chunk.
// ---------------------------------------------------------------------------
__global__ __launch_bounds__(128)
void fuse_kernel(const float* __restrict__ h, const int* __restrict__ routes,
                 const float* __restrict__ w, float* __restrict__ fused)
{
    const int s = blockIdx.x;
    const int b = blockIdx.y;
    const int tid = threadIdx.x;

    __shared__ float ws[PK];
    __shared__ int   rs[PK];
    if (tid < PK) {
        ws[tid] = w[s * PK + tid];
        rs[tid] = routes[s * PK + tid];
    }
    __syncthreads();

    const float* hb = h + (size_t)b * PS * PD;
    const int col = tid * 4;

    float4 acc = make_float4(0.f, 0.f, 0.f, 0.f);
#pragma unroll 4
    for (int k = 0; k < PK; k++) {
        float wk = ws[k];
        const float4 v = *(const float4*)&hb[(size_t)rs[k] * PD + col];
        acc.x = fmaf(wk, v.x, acc.x);
        acc.y = fmaf(wk, v.y, acc.y);
        acc.z = fmaf(wk, v.z, acc.z);
        acc.w = fmaf(wk, v.w, acc.w);
    }
    *(float4*)&fused[((size_t)b * PS + s) * PD + col] = acc;
}

// ---------------------------------------------------------------------------
// kernel_launch
// Inputs: 0: x (B,S,D) f32 | 1: routes (S,K) i32 | 2: distances (S,S) f32
//         3: W_in (D,D) f32 | 4: W_out (D,D) f32 | 5: b_out (D,) f32
// Output: (B,S,D) f32
// ---------------------------------------------------------------------------
extern "C" void kernel_launch(void* const* d_in, const int* in_sizes, int n_in,
                              void* d_out, int out_size)
{
    const float* x      = (const float*)d_in[0];
    const int*   routes = (const int*)  d_in[1];
    const float* dist   = (const float*)d_in[2];
    const float* W_in   = (const float*)d_in[3];
    const float* W_out  = (const float*)d_in[4];
    const float* b_out  = (const float*)d_in[5];
    float*       out    = (float*)d_out;

    float *h_ptr, *fused_ptr, *w_ptr;
    cudaGetSymbolAddress((void**)&h_ptr,     g_h);
    cudaGetSymbolAddress((void**)&fused_ptr, g_fused);
    cudaGetSymbolAddress((void**)&w_ptr,     g_w);

    const int M = PB * PS;   // 4096
    const int N = PD;        // 512
    const int Kd = PD;       // 512

    // 1) h = x @ W_in^T
    {
        dim3 grid(N / BN, M / BM);
        gemm_nt_kernel<false><<<grid, 256>>>(x, W_in, h_ptr, nullptr, nullptr, M, N, Kd);
    }
    // 2) softmax weights
    softmax_kernel<<<PS, PK>>>(routes, dist, w_ptr);

    // 3) gather-fuse
    {
        dim3 grid(PS, PB);
        fuse_kernel<<<grid, 128>>>(h_ptr, routes, w_ptr, fused_ptr);
    }
    // 4) out = fused @ W_out^T + b_out + x
    {
        dim3 grid(N / BN, M / BM);
        gemm_nt_kernel<true><<<grid, 256>>>(fused_ptr, W_out, out, b_out, x, M, N, Kd);
    }
}

// round 4
// speedup vs baseline: 1.7184x; 1.7184x over previous
#include <cuda_runtime.h>
#include <cuda_bf16.h>
#include <cstdint>

// Problem constants (B=2, S=2048, D=512, K=64)
#define PB 2
#define PS 2048
#define PD 512
#define PK 64
#define MT (PB * PS)   // 4096 rows total

// ---------------------------------------------------------------------------
// Scratch (device globals — no allocation allowed)
// ---------------------------------------------------------------------------
__device__ __align__(16) float         g_h[MT * PD];
__device__ __align__(16) float         g_w[PS * PK];
__device__ __align__(16) __nv_bfloat16 g_x_hi[MT * PD];
__device__ __align__(16) __nv_bfloat16 g_x_lo[MT * PD];
__device__ __align__(16) __nv_bfloat16 g_wi_hi[PD * PD];
__device__ __align__(16) __nv_bfloat16 g_wi_lo[PD * PD];
__device__ __align__(16) __nv_bfloat16 g_wo_hi[PD * PD];
__device__ __align__(16) __nv_bfloat16 g_wo_lo[PD * PD];
__device__ __align__(16) __nv_bfloat16 g_f_hi[MT * PD];
__device__ __align__(16) __nv_bfloat16 g_f_lo[MT * PD];

// ---------------------------------------------------------------------------
// PTX helpers (sm_80-level only — NO 'a'-gated instructions; the harness
// builds via compute_103 PTX which rejects tcgen05/TMEM)
// ---------------------------------------------------------------------------
__device__ __forceinline__ uint32_t smem_u32(const void* p) {
    uint32_t a;
    asm("{ .reg .u64 t; cvta.to.shared.u64 t, %1; cvt.u32.u64 %0, t; }" : "=r"(a) : "l"(p));
    return a;
}

#define LDSM4(r, addr) \
    asm volatile("ldmatrix.sync.aligned.m8n8.x4.shared.b16 {%0,%1,%2,%3}, [%4];" \
                 : "=r"((r)[0]), "=r"((r)[1]), "=r"((r)[2]), "=r"((r)[3]) : "r"(addr))

#define MMA16816(d, a, b0, b1) \
    asm volatile("mma.sync.aligned.m16n8k16.row.col.f32.bf16.bf16.f32 " \
                 "{%0,%1,%2,%3}, {%4,%5,%6,%7}, {%8,%9}, {%0,%1,%2,%3};" \
                 : "+f"((d)[0]), "+f"((d)[1]), "+f"((d)[2]), "+f"((d)[3]) \
                 : "r"((a)[0]), "r"((a)[1]), "r"((a)[2]), "r"((a)[3]), "r"(b0), "r"(b1))

#define CP16(dst, src) \
    asm volatile("cp.async.cg.shared.global [%0], [%1], 16;" :: "r"(dst), "l"(src))
#define CP_COMMIT()  asm volatile("cp.async.commit_group;" ::: "memory")
#define CP_WAIT(N)   asm volatile("cp.async.wait_group %0;" :: "n"(N) : "memory")

// ---------------------------------------------------------------------------
// Split-bf16 GEMM (NT): C[m,n] = sum_k A[m,k]*B[n,k]
//   A ~ Ahi+Alo, B ~ Bhi+Blo (bf16 each); C = Ahi*Bhi + Ahi*Blo + Alo*Bhi
// Tile 128x128, BK=16, 8 warps (4m x 2n), double-buffered cp.async smem.
// smem tile: 128 rows x 32B (k16 bf16), swizzle: unit' = unit ^ ((row>>2)&1)
// ---------------------------------------------------------------------------
#define GBM 128
#define GBN 128
#define GBK 16
#define NITER (PD / GBK)     // 32
#define TILEB 4096           // 128 * 32B
#define STAGEB (4 * TILEB)   // Ahi, Alo, Bhi, Blo

template <bool EPI>
__global__ __launch_bounds__(256)
void mma_gemm_kernel(const __nv_bfloat16* __restrict__ Ahi, const __nv_bfloat16* __restrict__ Alo,
                     const __nv_bfloat16* __restrict__ Bhi, const __nv_bfloat16* __restrict__ Blo,
                     float* __restrict__ C,
                     const float* __restrict__ bias, const float* __restrict__ resid)
{
    __shared__ __align__(128) char sm[2 * STAGEB];   // 32 KB
    const uint32_t sbase = smem_u32(sm);

    const int tid  = threadIdx.x;
    const int lane = tid & 31;
    const int wid  = tid >> 5;
    const int warpM = (wid & 3) * 32;
    const int warpN = (wid >> 2) * 64;
    const int blockM = blockIdx.y * GBM;
    const int blockN = blockIdx.x * GBN;

    // cp.async per-thread mapping: each thread owns (row, u) across all 4 tiles
    const int crow = tid >> 1;
    const int cu   = tid & 1;
    const uint32_t cdst = (uint32_t)(crow * 32 + ((cu ^ ((crow >> 2) & 1)) * 16));
    const size_t aoff = (size_t)(blockM + crow) * PD + cu * 8;
    const size_t boff = (size_t)(blockN + crow) * PD + cu * 8;

    // ldmatrix per-lane offsets
    const int mx = lane >> 3;
    const int lr = lane & 7;
    const int rA = (mx & 1) * 8 + lr;           // + warpM + mt*16
    const int uA = mx >> 1;
    const int rB = (mx >> 1) * 8 + lr;          // + warpN + np*16
    const int uB = mx & 1;
    const uint32_t offA = (uint32_t)((warpM + rA) * 32 + ((uA ^ ((rA >> 2) & 1)) * 16));
    const uint32_t offB = (uint32_t)((warpN + rB) * 32 + ((uB ^ ((rB >> 2) & 1)) * 16));

    float acc[2][8][4];
#pragma unroll
    for (int mt = 0; mt < 2; mt++)
#pragma unroll
        for (int nt = 0; nt < 8; nt++)
#pragma unroll
            for (int j = 0; j < 4; j++) acc[mt][nt][j] = 0.0f;

    // --- prologue: load k-chunk 0 into stage 0 ---
    {
        const uint32_t sd = sbase + cdst;
        CP16(sd + 0 * TILEB, Ahi + aoff);
        CP16(sd + 1 * TILEB, Alo + aoff);
        CP16(sd + 2 * TILEB, Bhi + boff);
        CP16(sd + 3 * TILEB, Blo + boff);
        CP_COMMIT();
    }

    for (int c = 0; c < NITER; c++) {
        if (c < NITER - 1) {
            const int kt = (c + 1) * GBK;
            const uint32_t sd = sbase + ((c + 1) & 1) * STAGEB + cdst;
            CP16(sd + 0 * TILEB, Ahi + aoff + kt);
            CP16(sd + 1 * TILEB, Alo + aoff + kt);
            CP16(sd + 2 * TILEB, Bhi + boff + kt);
            CP16(sd + 3 * TILEB, Blo + boff + kt);
            CP_COMMIT();
            CP_WAIT(1);
        } else {
            CP_WAIT(0);
        }
        __syncthreads();

        const uint32_t sb = sbase + (c & 1) * STAGEB;
        uint32_t ah[2][4], al[2][4];
#pragma unroll
        for (int mt = 0; mt < 2; mt++) {
            LDSM4(ah[mt], sb + 0 * TILEB + offA + mt * 512);
            LDSM4(al[mt], sb + 1 * TILEB + offA + mt * 512);
        }
#pragma unroll
        for (int np = 0; np < 4; np++) {
            uint32_t bh[4], bl[4];
            LDSM4(bh, sb + 2 * TILEB + offB + np * 512);
            LDSM4(bl, sb + 3 * TILEB + offB + np * 512);
#pragma unroll
            for (int sub = 0; sub < 2; sub++) {
                const int nt = np * 2 + sub;
                const uint32_t b0h = bh[sub * 2], b1h = bh[sub * 2 + 1];
                const uint32_t b0l = bl[sub * 2], b1l = bl[sub * 2 + 1];
#pragma unroll
                for (int mt = 0; mt < 2; mt++) {
                    MMA16816(acc[mt][nt], ah[mt], b0h, b1h);
                    MMA16816(acc[mt][nt], ah[mt], b0l, b1l);
                    MMA16816(acc[mt][nt], al[mt], b0h, b1h);
                }
            }
        }
        __syncthreads();
    }

    // --- epilogue ---
    const int g  = lane >> 2;
    const int tg = lane & 3;
#pragma unroll
    for (int mt = 0; mt < 2; mt++) {
#pragma unroll
        for (int nt = 0; nt < 8; nt++) {
            const int row = blockM + warpM + mt * 16 + g;
            const int col = blockN + warpN + nt * 8 + tg * 2;
            float2 v0 = make_float2(acc[mt][nt][0], acc[mt][nt][1]);
            float2 v1 = make_float2(acc[mt][nt][2], acc[mt][nt][3]);
            const size_t o0 = (size_t)row * PD + col;
            const size_t o1 = (size_t)(row + 8) * PD + col;
            if (EPI) {
                const float2 bb = *(const float2*)&bias[col];
                const float2 x0 = *(const float2*)&resid[o0];
                const float2 x1 = *(const float2*)&resid[o1];
                v0.x += bb.x + x0.x; v0.y += bb.y + x0.y;
                v1.x += bb.x + x1.x; v1.y += bb.y + x1.y;
            }
            *(float2*)&C[o0] = v0;
            *(float2*)&C[o1] = v1;
        }
    }
}

// ---------------------------------------------------------------------------
// Split fp32 -> (bf16 hi, bf16 lo)
// ---------------------------------------------------------------------------
__global__ __launch_bounds__(256)
void split_kernel(const float* __restrict__ src, __nv_bfloat16* __restrict__ hi,
                  __nv_bfloat16* __restrict__ lo, int n)
{
    const int i = (blockIdx.x * blockDim.x + threadIdx.x) * 4;
    if (i < n) {
        const float4 v = *(const float4*)(src + i);
        float vv[4] = {v.x, v.y, v.z, v.w};
        __align__(8) __nv_bfloat16 h4[4], l4[4];
#pragma unroll
        for (int j = 0; j < 4; j++) {
            h4[j] = __float2bfloat16(vv[j]);
            l4[j] = __float2bfloat16(vv[j] - __bfloat162float(h4[j]));
        }
        *(uint2*)(hi + i) = *(const uint2*)h4;
        *(uint2*)(lo + i) = *(const uint2*)l4;
    }
}

// ---------------------------------------------------------------------------
// Softmax: w[s,k] = softmax_k(-distances[s, routes[s,k]])
// ---------------------------------------------------------------------------
__global__ __launch_bounds__(PK)
void softmax_kernel(const int* __restrict__ routes, const float* __restrict__ dist,
                    float* __restrict__ w)
{
    const int s = blockIdx.x;
    const int t = threadIdx.x;
    __shared__ float red[PK];

    const int r = routes[s * PK + t];
    const float v = -dist[(size_t)s * PS + r];

    red[t] = v;
    __syncthreads();
#pragma unroll
    for (int off = PK / 2; off > 0; off >>= 1) {
        if (t < off) red[t] = fmaxf(red[t], red[t + off]);
        __syncthreads();
    }
    const float m = red[0];
    __syncthreads();

    const float e = __expf(v - m);
    red[t] = e;
    __syncthreads();
#pragma unroll
    for (int off = PK / 2; off > 0; off >>= 1) {
        if (t < off) red[t] += red[t + off];
        __syncthreads();
    }
    w[s * PK + t] = e / red[0];
}

// ---------------------------------------------------------------------------
// Gather-fuse: fused[b,s,:] = sum_k w[s,k] * h[b, routes[s,k], :]
// Emits split-bf16 pair directly (feeds GEMM2).
// ---------------------------------------------------------------------------
__global__ __launch_bounds__(128)
void fuse_kernel(const float* __restrict__ h, const int* __restrict__ routes,
                 const float* __restrict__ w,
                 __nv_bfloat16* __restrict__ f_hi, __nv_bfloat16* __restrict__ f_lo)
{
    const int s = blockIdx.x;
    const int b = blockIdx.y;
    const int tid = threadIdx.x;

    __shared__ float ws[PK];
    __shared__ int   rs[PK];
    if (tid < PK) {
        ws[tid] = w[s * PK + tid];
        rs[tid] = routes[s * PK + tid];
    }
    __syncthreads();

    const float* hb = h + (size_t)b * PS * PD;
    const int col = tid * 4;

    float4 acc = make_float4(0.f, 0.f, 0.f, 0.f);
#pragma unroll 4
    for (int k = 0; k < PK; k++) {
        const float wk = ws[k];
        const float4 v = *(const float4*)&hb[(size_t)rs[k] * PD + col];
        acc.x = fmaf(wk, v.x, acc.x);
        acc.y = fmaf(wk, v.y, acc.y);
        acc.z = fmaf(wk, v.z, acc.z);
        acc.w = fmaf(wk, v.w, acc.w);
    }

    const size_t o = ((size_t)b * PS + s) * PD + col;
    float aa[4] = {acc.x, acc.y, acc.z, acc.w};
    __align__(8) __nv_bfloat16 h4[4], l4[4];
#pragma unroll
    for (int j = 0; j < 4; j++) {
        h4[j] = __float2bfloat16(aa[j]);
        l4[j] = __float2bfloat16(aa[j] - __bfloat162float(h4[j]));
    }
    *(uint2*)(f_hi + o) = *(const uint2*)h4;
    *(uint2*)(f_lo + o) = *(const uint2*)l4;
}

// ---------------------------------------------------------------------------
// kernel_launch
// Inputs: 0: x (B,S,D) f32 | 1: routes (S,K) i32 | 2: distances (S,S) f32
//         3: W_in (D,D) f32 | 4: W_out (D,D) f32 | 5: b_out (D,) f32
// ---------------------------------------------------------------------------
extern "C" void kernel_launch(void* const* d_in, const int* in_sizes, int n_in,
                              void* d_out, int out_size)
{
    const float* x      = (const float*)d_in[0];
    const int*   routes = (const int*)  d_in[1];
    const float* dist   = (const float*)d_in[2];
    const float* W_in   = (const float*)d_in[3];
    const float* W_out  = (const float*)d_in[4];
    const float* b_out  = (const float*)d_in[5];
    float*       out    = (float*)d_out;

    float *h_ptr, *w_ptr;
    __nv_bfloat16 *xh, *xl, *wih, *wil, *woh, *wol, *fh, *fl;
    cudaGetSymbolAddress((void**)&h_ptr, g_h);
    cudaGetSymbolAddress((void**)&w_ptr, g_w);
    cudaGetSymbolAddress((void**)&xh,  g_x_hi);
    cudaGetSymbolAddress((void**)&xl,  g_x_lo);
    cudaGetSymbolAddress((void**)&wih, g_wi_hi);
    cudaGetSymbolAddress((void**)&wil, g_wi_lo);
    cudaGetSymbolAddress((void**)&woh, g_wo_hi);
    cudaGetSymbolAddress((void**)&wol, g_wo_lo);
    cudaGetSymbolAddress((void**)&fh,  g_f_hi);
    cudaGetSymbolAddress((void**)&fl,  g_f_lo);

    // 0) splits
    split_kernel<<<(MT * PD) / 1024, 256>>>(x, xh, xl, MT * PD);
    split_kernel<<<(PD * PD) / 1024, 256>>>(W_in, wih, wil, PD * PD);
    split_kernel<<<(PD * PD) / 1024, 256>>>(W_out, woh, wol, PD * PD);

    // 1) h = x @ W_in^T
    {
        dim3 grid(PD / GBN, MT / GBM);   // 4 x 32 = 128 CTAs
        mma_gemm_kernel<false><<<grid, 256>>>(xh, xl, wih, wil, h_ptr, nullptr, nullptr);
    }

    // 2) softmax weights
    softmax_kernel<<<PS, PK>>>(routes, dist, w_ptr);

    // 3) gather-fuse -> split-bf16 fused
    {
        dim3 grid(PS, PB);
        fuse_kernel<<<grid, 128>>>(h_ptr, routes, w_ptr, fh, fl);
    }

    // 4) out = fused @ W_out^T + b_out + x
    {
        dim3 grid(PD / GBN, MT / GBM);
        mma_gemm_kernel<true><<<grid, 256>>>(fh, fl, woh, wol, out, b_out, x);
    }
}

// round 5
// speedup vs baseline: 1.7912x; 1.0424x over previous
#include <cuda_runtime.h>
#include <cuda_bf16.h>
#include <cstdint>

// Problem constants (B=2, S=2048, D=512, K=64)
#define PB 2
#define PS 2048
#define PD 512
#define PK 64
#define MT (PB * PS)   // 4096 rows total

// ---------------------------------------------------------------------------
// Scratch (device globals — no allocation allowed)
// ---------------------------------------------------------------------------
__device__ __align__(16) float         g_h[MT * PD];
__device__ __align__(16) float         g_w[PS * PK];
__device__ __align__(16) __nv_bfloat16 g_x_hi[MT * PD];
__device__ __align__(16) __nv_bfloat16 g_x_lo[MT * PD];
__device__ __align__(16) __nv_bfloat16 g_wi_hi[PD * PD];
__device__ __align__(16) __nv_bfloat16 g_wi_lo[PD * PD];
__device__ __align__(16) __nv_bfloat16 g_wo_hi[PD * PD];
__device__ __align__(16) __nv_bfloat16 g_wo_lo[PD * PD];
__device__ __align__(16) __nv_bfloat16 g_f_hi[MT * PD];
__device__ __align__(16) __nv_bfloat16 g_f_lo[MT * PD];

// ---------------------------------------------------------------------------
// PTX helpers (sm_80-level only — harness compiles via compute_103 PTX,
// which rejects all 'a'-gated tcgen05/TMEM instructions)
// ---------------------------------------------------------------------------
__device__ __forceinline__ uint32_t smem_u32(const void* p) {
    uint32_t a;
    asm("{ .reg .u64 t; cvta.to.shared.u64 t, %1; cvt.u32.u64 %0, t; }" : "=r"(a) : "l"(p));
    return a;
}

#define LDSM4(r, addr) \
    asm volatile("ldmatrix.sync.aligned.m8n8.x4.shared.b16 {%0,%1,%2,%3}, [%4];" \
                 : "=r"((r)[0]), "=r"((r)[1]), "=r"((r)[2]), "=r"((r)[3]) : "r"(addr))

#define MMA16816(d, a, b0, b1) \
    asm volatile("mma.sync.aligned.m16n8k16.row.col.f32.bf16.bf16.f32 " \
                 "{%0,%1,%2,%3}, {%4,%5,%6,%7}, {%8,%9}, {%0,%1,%2,%3};" \
                 : "+f"((d)[0]), "+f"((d)[1]), "+f"((d)[2]), "+f"((d)[3]) \
                 : "r"((a)[0]), "r"((a)[1]), "r"((a)[2]), "r"((a)[3]), "r"(b0), "r"(b1))

#define CP16(dst, src) \
    asm volatile("cp.async.cg.shared.global [%0], [%1], 16;" :: "r"(dst), "l"(src))
#define CP_COMMIT()  asm volatile("cp.async.commit_group;" ::: "memory")
#define CP_WAIT(N)   asm volatile("cp.async.wait_group %0;" :: "n"(N) : "memory")

// ---------------------------------------------------------------------------
// Split-bf16 GEMM (NT): C[m,n] = sum_k A[m,k]*B[n,k]
//   A ~ Ahi+Alo, B ~ Bhi+Blo; C = Ahi*Bhi + Ahi*Blo + Alo*Bhi (fp32 acc)
// Tile 128x128, BK=32, 8 warps (4m x 2n), 3-stage cp.async ring,
// ONE __syncthreads per K-iter.
// smem tile: 128 rows x 64B; swizzle: u' = u ^ ((row>>1)&3)
// ---------------------------------------------------------------------------
#define GBM 128
#define GBN 128
#define GBK 32
#define NITER (PD / GBK)       // 16
#define STAGES 3
#define TILEB (128 * 64)       // 8192 B
#define STAGEB (4 * TILEB)     // 32768 B : Ahi, Alo, Bhi, Blo
#define GEMM_SMEM (STAGES * STAGEB)   // 98304 B (dynamic)

__device__ __forceinline__ uint32_t swz(int row, int u) {
    return (uint32_t)(row * 64 + ((u ^ ((row >> 1) & 3)) * 16));
}

template <bool EPI>
__global__ __launch_bounds__(256, 1)
void mma_gemm_kernel(const __nv_bfloat16* __restrict__ Ahi, const __nv_bfloat16* __restrict__ Alo,
                     const __nv_bfloat16* __restrict__ Bhi, const __nv_bfloat16* __restrict__ Blo,
                     float* __restrict__ C,
                     const float* __restrict__ bias, const float* __restrict__ resid)
{
    extern __shared__ __align__(128) char sm[];
    const uint32_t sbase = smem_u32(sm);

    const int tid  = threadIdx.x;
    const int lane = tid & 31;
    const int wid  = tid >> 5;
    const int warpM = (wid & 3) * 32;
    const int warpN = (wid >> 2) * 64;
    const int blockM = blockIdx.y * GBM;
    const int blockN = blockIdx.x * GBN;

    // cp.async mapping: per tile, 512 16B-units; thread owns units tid*2, tid*2+1
    const int i0row = (tid * 2) >> 2;        // both units share this row
    const int i0u   = (tid * 2) & 3;         // 0 or 2
    const uint32_t cd0 = swz(i0row, i0u);
    const uint32_t cd1 = swz(i0row, i0u + 1);
    const size_t aoff0 = (size_t)(blockM + i0row) * PD + i0u * 8;
    const size_t boff0 = (size_t)(blockN + i0row) * PD + i0u * 8;

    // ldmatrix lane mapping (identical fragment layout to the R4-proven kernel)
    const int mx = lane >> 3;
    const int lr = lane & 7;
    const int rA = (mx & 1) * 8 + lr;        // + warpM (+ mt*16: additive, swz-safe)
    const int uA = mx >> 1;                  // + hk*2
    const int rB = (mx >> 1) * 8 + lr;       // + warpN (+ np*16)
    const int uB = mx & 1;                   // + hk*2
    // warpM/mt*16/np*16 are multiples of 8 rows -> don't change ((row>>1)&3)
    const uint32_t offA0 = (uint32_t)(warpM + rA) * 64 + ((0 + uA) ^ ((rA >> 1) & 3)) * 16;
    const uint32_t offA1 = (uint32_t)(warpM + rA) * 64 + ((2 + uA) ^ ((rA >> 1) & 3)) * 16;
    const uint32_t offB0 = (uint32_t)(warpN + rB) * 64 + ((0 + uB) ^ ((rB >> 1) & 3)) * 16;
    const uint32_t offB1 = (uint32_t)(warpN + rB) * 64 + ((2 + uB) ^ ((rB >> 1) & 3)) * 16;

    float acc[2][8][4];
#pragma unroll
    for (int mt = 0; mt < 2; mt++)
#pragma unroll
        for (int nt = 0; nt < 8; nt++)
#pragma unroll
            for (int j = 0; j < 4; j++) acc[mt][nt][j] = 0.0f;

    // Issue one chunk's loads into a stage
    auto issue = [&](int chunk, int stage) {
        const int kt = chunk * GBK;
        const uint32_t sd = sbase + stage * STAGEB;
        CP16(sd + 0 * TILEB + cd0, Ahi + aoff0 + kt);
        CP16(sd + 0 * TILEB + cd1, Ahi + aoff0 + kt + 8);
        CP16(sd + 1 * TILEB + cd0, Alo + aoff0 + kt);
        CP16(sd + 1 * TILEB + cd1, Alo + aoff0 + kt + 8);
        CP16(sd + 2 * TILEB + cd0, Bhi + boff0 + kt);
        CP16(sd + 2 * TILEB + cd1, Bhi + boff0 + kt + 8);
        CP16(sd + 3 * TILEB + cd0, Blo + boff0 + kt);
        CP16(sd + 3 * TILEB + cd1, Blo + boff0 + kt + 8);
    };

    // prologue: stages 0,1
    issue(0, 0); CP_COMMIT();
    issue(1, 1); CP_COMMIT();

    for (int c = 0; c < NITER; c++) {
        CP_WAIT(1);
        __syncthreads();

        // keep group count uniform: dummy commit when out of chunks
        if (c + 2 < NITER) issue(c + 2, (c + 2) % STAGES);
        CP_COMMIT();

        const uint32_t sb = sbase + (c % STAGES) * STAGEB;

#pragma unroll
        for (int hk = 0; hk < 2; hk++) {
            const uint32_t oA = hk ? offA1 : offA0;
            const uint32_t oB = hk ? offB1 : offB0;
            uint32_t ah[2][4], al[2][4];
#pragma unroll
            for (int mt = 0; mt < 2; mt++) {
                LDSM4(ah[mt], sb + 0 * TILEB + oA + mt * 1024);
                LDSM4(al[mt], sb + 1 * TILEB + oA + mt * 1024);
            }
#pragma unroll
            for (int np = 0; np < 4; np++) {
                uint32_t bh[4], bl[4];
                LDSM4(bh, sb + 2 * TILEB + oB + np * 1024);
                LDSM4(bl, sb + 3 * TILEB + oB + np * 1024);
#pragma unroll
                for (int sub = 0; sub < 2; sub++) {
                    const int nt = np * 2 + sub;
                    const uint32_t b0h = bh[sub * 2], b1h = bh[sub * 2 + 1];
                    const uint32_t b0l = bl[sub * 2], b1l = bl[sub * 2 + 1];
#pragma unroll
                    for (int mt = 0; mt < 2; mt++) {
                        MMA16816(acc[mt][nt], ah[mt], b0h, b1h);
                        MMA16816(acc[mt][nt], ah[mt], b0l, b1l);
                        MMA16816(acc[mt][nt], al[mt], b0h, b1h);
                    }
                }
            }
        }
        __syncthreads();
    }

    // --- epilogue ---
    const int g  = lane >> 2;
    const int tg = lane & 3;
#pragma unroll
    for (int mt = 0; mt < 2; mt++) {
#pragma unroll
        for (int nt = 0; nt < 8; nt++) {
            const int row = blockM + warpM + mt * 16 + g;
            const int col = blockN + warpN + nt * 8 + tg * 2;
            float2 v0 = make_float2(acc[mt][nt][0], acc[mt][nt][1]);
            float2 v1 = make_float2(acc[mt][nt][2], acc[mt][nt][3]);
            const size_t o0 = (size_t)row * PD + col;
            const size_t o1 = (size_t)(row + 8) * PD + col;
            if (EPI) {
                const float2 bb = *(const float2*)&bias[col];
                const float2 x0 = *(const float2*)&resid[o0];
                const float2 x1 = *(const float2*)&resid[o1];
                v0.x += bb.x + x0.x; v0.y += bb.y + x0.y;
                v1.x += bb.x + x1.x; v1.y += bb.y + x1.y;
            }
            *(float2*)&C[o0] = v0;
            *(float2*)&C[o1] = v1;
        }
    }
}

// ---------------------------------------------------------------------------
// Split fp32 -> (bf16 hi, bf16 lo)
// ---------------------------------------------------------------------------
__global__ __launch_bounds__(256)
void split_kernel(const float* __restrict__ src, __nv_bfloat16* __restrict__ hi,
                  __nv_bfloat16* __restrict__ lo, int n)
{
    const int i = (blockIdx.x * blockDim.x + threadIdx.x) * 4;
    if (i < n) {
        const float4 v = *(const float4*)(src + i);
        float vv[4] = {v.x, v.y, v.z, v.w};
        __align__(8) __nv_bfloat16 h4[4], l4[4];
#pragma unroll
        for (int j = 0; j < 4; j++) {
            h4[j] = __float2bfloat16(vv[j]);
            l4[j] = __float2bfloat16(vv[j] - __bfloat162float(h4[j]));
        }
        *(uint2*)(hi + i) = *(const uint2*)h4;
        *(uint2*)(lo + i) = *(const uint2*)l4;
    }
}

// ---------------------------------------------------------------------------
// Softmax: w[s,k] = softmax_k(-distances[s, routes[s,k]])
// ---------------------------------------------------------------------------
__global__ __launch_bounds__(PK)
void softmax_kernel(const int* __restrict__ routes, const float* __restrict__ dist,
                    float* __restrict__ w)
{
    const int s = blockIdx.x;
    const int t = threadIdx.x;
    __shared__ float red[PK];

    const int r = routes[s * PK + t];
    const float v = -dist[(size_t)s * PS + r];

    red[t] = v;
    __syncthreads();
#pragma unroll
    for (int off = PK / 2; off > 0; off >>= 1) {
        if (t < off) red[t] = fmaxf(red[t], red[t + off]);
        __syncthreads();
    }
    const float m = red[0];
    __syncthreads();

    const float e = __expf(v - m);
    red[t] = e;
    __syncthreads();
#pragma unroll
    for (int off = PK / 2; off > 0; off >>= 1) {
        if (t < off) red[t] += red[t + off];
        __syncthreads();
    }
    w[s * PK + t] = e / red[0];
}

// ---------------------------------------------------------------------------
// Gather-fuse: fused[b,s,:] = sum_k w[s,k] * h[b, routes[s,k], :]
// Emits split-bf16 pair directly (feeds GEMM2).
// ---------------------------------------------------------------------------
__global__ __launch_bounds__(128)
void fuse_kernel(const float* __restrict__ h, const int* __restrict__ routes,
                 const float* __restrict__ w,
                 __nv_bfloat16* __restrict__ f_hi, __nv_bfloat16* __restrict__ f_lo)
{
    const int s = blockIdx.x;
    const int b = blockIdx.y;
    const int tid = threadIdx.x;

    __shared__ float ws[PK];
    __shared__ int   rs[PK];
    if (tid < PK) {
        ws[tid] = w[s * PK + tid];
        rs[tid] = routes[s * PK + tid];
    }
    __syncthreads();

    const float* hb = h + (size_t)b * PS * PD;
    const int col = tid * 4;

    float4 acc = make_float4(0.f, 0.f, 0.f, 0.f);
#pragma unroll 8
    for (int k = 0; k < PK; k++) {
        const float wk = ws[k];
        const float4 v = *(const float4*)&hb[(size_t)rs[k] * PD + col];
        acc.x = fmaf(wk, v.x, acc.x);
        acc.y = fmaf(wk, v.y, acc.y);
        acc.z = fmaf(wk, v.z, acc.z);
        acc.w = fmaf(wk, v.w, acc.w);
    }

    const size_t o = ((size_t)b * PS + s) * PD + col;
    float aa[4] = {acc.x, acc.y, acc.z, acc.w};
    __align__(8) __nv_bfloat16 h4[4], l4[4];
#pragma unroll
    for (int j = 0; j < 4; j++) {
        h4[j] = __float2bfloat16(aa[j]);
        l4[j] = __float2bfloat16(aa[j] - __bfloat162float(h4[j]));
    }
    *(uint2*)(f_hi + o) = *(const uint2*)h4;
    *(uint2*)(f_lo + o) = *(const uint2*)l4;
}

// ---------------------------------------------------------------------------
// kernel_launch
// Inputs: 0: x (B,S,D) f32 | 1: routes (S,K) i32 | 2: distances (S,S) f32
//         3: W_in (D,D) f32 | 4: W_out (D,D) f32 | 5: b_out (D,) f32
// ---------------------------------------------------------------------------
extern "C" void kernel_launch(void* const* d_in, const int* in_sizes, int n_in,
                              void* d_out, int out_size)
{
    const float* x      = (const float*)d_in[0];
    const int*   routes = (const int*)  d_in[1];
    const float* dist   = (const float*)d_in[2];
    const float* W_in   = (const float*)d_in[3];
    const float* W_out  = (const float*)d_in[4];
    const float* b_out  = (const float*)d_in[5];
    float*       out    = (float*)d_out;

    float *h_ptr, *w_ptr;
    __nv_bfloat16 *xh, *xl, *wih, *wil, *woh, *wol, *fh, *fl;
    cudaGetSymbolAddress((void**)&h_ptr, g_h);
    cudaGetSymbolAddress((void**)&w_ptr, g_w);
    cudaGetSymbolAddress((void**)&xh,  g_x_hi);
    cudaGetSymbolAddress((void**)&xl,  g_x_lo);
    cudaGetSymbolAddress((void**)&wih, g_wi_hi);
    cudaGetSymbolAddress((void**)&wil, g_wi_lo);
    cudaGetSymbolAddress((void**)&woh, g_wo_hi);
    cudaGetSymbolAddress((void**)&wol, g_wo_lo);
    cudaGetSymbolAddress((void**)&fh,  g_f_hi);
    cudaGetSymbolAddress((void**)&fl,  g_f_lo);

    static bool attr_set = false;
    if (!attr_set) {
        cudaFuncSetAttribute(mma_gemm_kernel<false>,
                             cudaFuncAttributeMaxDynamicSharedMemorySize, GEMM_SMEM);
        cudaFuncSetAttribute(mma_gemm_kernel<true>,
                             cudaFuncAttributeMaxDynamicSharedMemorySize, GEMM_SMEM);
        attr_set = true;
    }

    // 0) splits
    split_kernel<<<(MT * PD) / 1024, 256>>>(x, xh, xl, MT * PD);
    split_kernel<<<(PD * PD) / 1024, 256>>>(W_in, wih, wil, PD * PD);
    split_kernel<<<(PD * PD) / 1024, 256>>>(W_out, woh, wol, PD * PD);

    // 1) h = x @ W_in^T
    {
        dim3 grid(PD / GBN, MT / GBM);   // 4 x 32 = 128 CTAs = one wave
        mma_gemm_kernel<false><<<grid, 256, GEMM_SMEM>>>(xh, xl, wih, wil, h_ptr, nullptr, nullptr);
    }

    // 2) softmax weights
    softmax_kernel<<<PS, PK>>>(routes, dist, w_ptr);

    // 3) gather-fuse -> split-bf16 fused
    {
        dim3 grid(PS, PB);
        fuse_kernel<<<grid, 128>>>(h_ptr, routes, w_ptr, fh, fl);
    }

    // 4) out = fused @ W_out^T + b_out + x
    {
        dim3 grid(PD / GBN, MT / GBM);
        mma_gemm_kernel<true><<<grid, 256, GEMM_SMEM>>>(fh, fl, woh, wol, out, b_out, x);
    }
}

// round 6
// speedup vs baseline: 1.9693x; 1.0994x over previous
#include <cuda_runtime.h>
#include <cuda_bf16.h>
#include <cstdint>

// Problem constants (B=2, S=2048, D=512, K=64)
#define PB 2
#define PS 2048
#define PD 512
#define PK 64
#define MT (PB * PS)   // 4096 rows total

// ---------------------------------------------------------------------------
// Scratch (device globals — no allocation allowed)
// ---------------------------------------------------------------------------
__device__ __align__(16) float         g_h[MT * PD];
__device__ __align__(16) float         g_w[PS * PK];
__device__ __align__(16) __nv_bfloat16 g_x_hi[MT * PD];
__device__ __align__(16) __nv_bfloat16 g_x_lo[MT * PD];
__device__ __align__(16) __nv_bfloat16 g_wi_hi[PD * PD];
__device__ __align__(16) __nv_bfloat16 g_wi_lo[PD * PD];
__device__ __align__(16) __nv_bfloat16 g_wo_hi[PD * PD];
__device__ __align__(16) __nv_bfloat16 g_wo_lo[PD * PD];
__device__ __align__(16) __nv_bfloat16 g_f_hi[MT * PD];
__device__ __align__(16) __nv_bfloat16 g_f_lo[MT * PD];

// ---------------------------------------------------------------------------
// PTX helpers (sm_80-level only — harness compiles via compute_103 PTX,
// which rejects all 'a'-gated tcgen05/TMEM instructions)
// ---------------------------------------------------------------------------
__device__ __forceinline__ uint32_t smem_u32(const void* p) {
    uint32_t a;
    asm("{ .reg .u64 t; cvta.to.shared.u64 t, %1; cvt.u32.u64 %0, t; }" : "=r"(a) : "l"(p));
    return a;
}

#define LDSM4(r, addr) \
    asm volatile("ldmatrix.sync.aligned.m8n8.x4.shared.b16 {%0,%1,%2,%3}, [%4];" \
                 : "=r"((r)[0]), "=r"((r)[1]), "=r"((r)[2]), "=r"((r)[3]) : "r"(addr))

#define MMA16816(d, a, b0, b1) \
    asm volatile("mma.sync.aligned.m16n8k16.row.col.f32.bf16.bf16.f32 " \
                 "{%0,%1,%2,%3}, {%4,%5,%6,%7}, {%8,%9}, {%0,%1,%2,%3};" \
                 : "+f"((d)[0]), "+f"((d)[1]), "+f"((d)[2]), "+f"((d)[3]) \
                 : "r"((a)[0]), "r"((a)[1]), "r"((a)[2]), "r"((a)[3]), "r"(b0), "r"(b1))

#define CP16(dst, src) \
    asm volatile("cp.async.cg.shared.global [%0], [%1], 16;" :: "r"(dst), "l"(src))
#define CP_COMMIT()  asm volatile("cp.async.commit_group;" ::: "memory")
#define CP_WAIT(N)   asm volatile("cp.async.wait_group %0;" :: "n"(N) : "memory")

// ---------------------------------------------------------------------------
// Split-bf16 GEMM (NT): C[m,n] = sum_k A[m,k]*B[n,k]
//   A ~ Ahi+Alo, B ~ Bhi+Blo; C = Ahi*Bhi + Ahi*Blo + Alo*Bhi (fp32 acc)
// Tile 128x64, BK=32, 8 warps (4m x 2n, warp tile 32x32),
// 3-stage cp.async ring, one __syncthreads per K-iter, 2 CTAs/SM.
// smem row = 64B; swizzle u' = u ^ ((row>>1)&3)
// ---------------------------------------------------------------------------
#define GBM 128
#define GBN 64
#define GBK 32
#define NITER (PD / GBK)       // 16
#define STAGES 3
#define ATILEB (128 * 64)      // 8192 B per A tile (hi or lo)
#define BTILEB (64 * 64)       // 4096 B per B tile
#define STAGEB (2 * ATILEB + 2 * BTILEB)   // 24576 B
#define GEMM_SMEM (STAGES * STAGEB)        // 73728 B

__device__ __forceinline__ uint32_t swz(int row, int u) {
    return (uint32_t)(row * 64 + ((u ^ ((row >> 1) & 3)) * 16));
}

template <bool EPI>
__global__ __launch_bounds__(256, 2)
void mma_gemm_kernel(const __nv_bfloat16* __restrict__ Ahi, const __nv_bfloat16* __restrict__ Alo,
                     const __nv_bfloat16* __restrict__ Bhi, const __nv_bfloat16* __restrict__ Blo,
                     float* __restrict__ C,
                     const float* __restrict__ bias, const float* __restrict__ resid)
{
    extern __shared__ __align__(128) char sm[];
    const uint32_t sbase = smem_u32(sm);

    const int tid  = threadIdx.x;
    const int lane = tid & 31;
    const int wid  = tid >> 5;
    const int warpM = (wid & 3) * 32;
    const int warpN = (wid >> 2) * 32;
    const int blockM = blockIdx.y * GBM;
    const int blockN = blockIdx.x * GBN;

    // cp.async mapping
    // A tiles (128 rows x 4 units): thread owns units 2t, 2t+1 (same row)
    const int arow = tid >> 1;
    const int au   = (tid & 1) * 2;
    const uint32_t acd0 = swz(arow, au);
    const uint32_t acd1 = swz(arow, au + 1);
    const size_t aoff = (size_t)(blockM + arow) * PD + au * 8;
    // B tiles (64 rows x 4 units): thread owns unit t (t < 256)
    const int brow = tid >> 2;
    const int bu   = tid & 3;
    const uint32_t bcd = swz(brow, bu);
    const size_t boff = (size_t)(blockN + brow) * PD + bu * 8;

    // ldmatrix lane mapping (fragment layout identical to proven R4/R5 kernels)
    const int mx = lane >> 3;
    const int lr = lane & 7;
    const int rA = (mx & 1) * 8 + lr;
    const int uA = mx >> 1;
    const int rB = (mx >> 1) * 8 + lr;
    const int uB = mx & 1;
    const uint32_t offA0 = (uint32_t)(warpM + rA) * 64 + ((0 + uA) ^ ((rA >> 1) & 3)) * 16;
    const uint32_t offA1 = (uint32_t)(warpM + rA) * 64 + ((2 + uA) ^ ((rA >> 1) & 3)) * 16;
    const uint32_t offB0 = (uint32_t)(warpN + rB) * 64 + ((0 + uB) ^ ((rB >> 1) & 3)) * 16;
    const uint32_t offB1 = (uint32_t)(warpN + rB) * 64 + ((2 + uB) ^ ((rB >> 1) & 3)) * 16;

    float acc[2][4][4];
#pragma unroll
    for (int mt = 0; mt < 2; mt++)
#pragma unroll
        for (int nt = 0; nt < 4; nt++)
#pragma unroll
            for (int j = 0; j < 4; j++) acc[mt][nt][j] = 0.0f;

    auto issue = [&](int chunk, int stage) {
        const int kt = chunk * GBK;
        const uint32_t sd = sbase + stage * STAGEB;
        CP16(sd + 0 * ATILEB + acd0, Ahi + aoff + kt);
        CP16(sd + 0 * ATILEB + acd1, Ahi + aoff + kt + 8);
        CP16(sd + 1 * ATILEB + acd0, Alo + aoff + kt);
        CP16(sd + 1 * ATILEB + acd1, Alo + aoff + kt + 8);
        CP16(sd + 2 * ATILEB + bcd, Bhi + boff + kt);
        CP16(sd + 2 * ATILEB + BTILEB + bcd, Blo + boff + kt);
    };

    issue(0, 0); CP_COMMIT();
    issue(1, 1); CP_COMMIT();

    for (int c = 0; c < NITER; c++) {
        CP_WAIT(1);
        __syncthreads();

        if (c + 2 < NITER) issue(c + 2, (c + 2) % STAGES);
        CP_COMMIT();

        const uint32_t sb = sbase + (c % STAGES) * STAGEB;

#pragma unroll
        for (int hk = 0; hk < 2; hk++) {
            const uint32_t oA = hk ? offA1 : offA0;
            const uint32_t oB = hk ? offB1 : offB0;
            uint32_t ah[2][4], al[2][4];
#pragma unroll
            for (int mt = 0; mt < 2; mt++) {
                LDSM4(ah[mt], sb + 0 * ATILEB + oA + mt * 1024);
                LDSM4(al[mt], sb + 1 * ATILEB + oA + mt * 1024);
            }
#pragma unroll
            for (int np = 0; np < 2; np++) {
                uint32_t bh[4], bl[4];
                LDSM4(bh, sb + 2 * ATILEB + oB + np * 1024);
                LDSM4(bl, sb + 2 * ATILEB + BTILEB + oB + np * 1024);
#pragma unroll
                for (int sub = 0; sub < 2; sub++) {
                    const int nt = np * 2 + sub;
                    const uint32_t b0h = bh[sub * 2], b1h = bh[sub * 2 + 1];
                    const uint32_t b0l = bl[sub * 2], b1l = bl[sub * 2 + 1];
#pragma unroll
                    for (int mt = 0; mt < 2; mt++) {
                        MMA16816(acc[mt][nt], ah[mt], b0h, b1h);
                        MMA16816(acc[mt][nt], ah[mt], b0l, b1l);
                        MMA16816(acc[mt][nt], al[mt], b0h, b1h);
                    }
                }
            }
        }
        __syncthreads();
    }

    // --- epilogue ---
    const int g  = lane >> 2;
    const int tg = lane & 3;
#pragma unroll
    for (int mt = 0; mt < 2; mt++) {
#pragma unroll
        for (int nt = 0; nt < 4; nt++) {
            const int row = blockM + warpM + mt * 16 + g;
            const int col = blockN + warpN + nt * 8 + tg * 2;
            float2 v0 = make_float2(acc[mt][nt][0], acc[mt][nt][1]);
            float2 v1 = make_float2(acc[mt][nt][2], acc[mt][nt][3]);
            const size_t o0 = (size_t)row * PD + col;
            const size_t o1 = (size_t)(row + 8) * PD + col;
            if (EPI) {
                const float2 bb = *(const float2*)&bias[col];
                const float2 x0 = *(const float2*)&resid[o0];
                const float2 x1 = *(const float2*)&resid[o1];
                v0.x += bb.x + x0.x; v0.y += bb.y + x0.y;
                v1.x += bb.x + x1.x; v1.y += bb.y + x1.y;
            }
            *(float2*)&C[o0] = v0;
            *(float2*)&C[o1] = v1;
        }
    }
}

// ---------------------------------------------------------------------------
// Merged split: x, W_in, W_out -> (hi, lo) bf16 pairs, one launch
// ---------------------------------------------------------------------------
__device__ __forceinline__ void split4(const float* src, __nv_bfloat16* hi,
                                       __nv_bfloat16* lo, int i)
{
    const float4 v = *(const float4*)(src + i);
    float vv[4] = {v.x, v.y, v.z, v.w};
    __align__(8) __nv_bfloat16 h4[4], l4[4];
#pragma unroll
    for (int j = 0; j < 4; j++) {
        h4[j] = __float2bfloat16(vv[j]);
        l4[j] = __float2bfloat16(vv[j] - __bfloat162float(h4[j]));
    }
    *(uint2*)(hi + i) = *(const uint2*)h4;
    *(uint2*)(lo + i) = *(const uint2*)l4;
}

#define NX (MT * PD)      // 2097152
#define NW (PD * PD)      // 262144
#define SPLIT_THREADS ((NX + 2 * NW) / 4)   // 655360

__global__ __launch_bounds__(256)
void split3_kernel(const float* __restrict__ x,  __nv_bfloat16* __restrict__ xh,  __nv_bfloat16* __restrict__ xl,
                   const float* __restrict__ Wi, __nv_bfloat16* __restrict__ wih, __nv_bfloat16* __restrict__ wil,
                   const float* __restrict__ Wo, __nv_bfloat16* __restrict__ woh, __nv_bfloat16* __restrict__ wol)
{
    const int t = blockIdx.x * blockDim.x + threadIdx.x;
    const int i = t * 4;
    if (i < NX) {
        split4(x, xh, xl, i);
    } else if (i < NX + NW) {
        split4(Wi, wih, wil, i - NX);
    } else {
        split4(Wo, woh, wol, i - NX - NW);
    }
}

// ---------------------------------------------------------------------------
// Softmax: w[s,k] = softmax_k(-distances[s, routes[s,k]])
// ---------------------------------------------------------------------------
__global__ __launch_bounds__(PK)
void softmax_kernel(const int* __restrict__ routes, const float* __restrict__ dist,
                    float* __restrict__ w)
{
    const int s = blockIdx.x;
    const int t = threadIdx.x;
    __shared__ float red[PK];

    const int r = routes[s * PK + t];
    const float v = -dist[(size_t)s * PS + r];

    red[t] = v;
    __syncthreads();
#pragma unroll
    for (int off = PK / 2; off > 0; off >>= 1) {
        if (t < off) red[t] = fmaxf(red[t], red[t + off]);
        __syncthreads();
    }
    const float m = red[0];
    __syncthreads();

    const float e = __expf(v - m);
    red[t] = e;
    __syncthreads();
#pragma unroll
    for (int off = PK / 2; off > 0; off >>= 1) {
        if (t < off) red[t] += red[t + off];
        __syncthreads();
    }
    w[s * PK + t] = e / red[0];
}

// ---------------------------------------------------------------------------
// Gather-fuse: fused[b,s,:] = sum_k w[s,k] * h[b, routes[s,k], :]
// One block per s, 256 threads: lower half b=0, upper half b=1.
// Emits split-bf16 pair directly (feeds GEMM2).
// ---------------------------------------------------------------------------
__global__ __launch_bounds__(256)
void fuse_kernel(const float* __restrict__ h, const int* __restrict__ routes,
                 const float* __restrict__ w,
                 __nv_bfloat16* __restrict__ f_hi, __nv_bfloat16* __restrict__ f_lo)
{
    const int s = blockIdx.x;
    const int tid = threadIdx.x;
    const int b = tid >> 7;          // 0 or 1
    const int ct = tid & 127;        // column-chunk thread

    __shared__ float ws[PK];
    __shared__ int   rs[PK];
    if (tid < PK) {
        ws[tid] = w[s * PK + tid];
        rs[tid] = routes[s * PK + tid];
    }
    __syncthreads();

    const float* hb = h + (size_t)b * PS * PD;
    const int col = ct * 4;

    float4 acc = make_float4(0.f, 0.f, 0.f, 0.f);
#pragma unroll 8
    for (int k = 0; k < PK; k++) {
        const float wk = ws[k];
        const float4 v = *(const float4*)&hb[(size_t)rs[k] * PD + col];
        acc.x = fmaf(wk, v.x, acc.x);
        acc.y = fmaf(wk, v.y, acc.y);
        acc.z = fmaf(wk, v.z, acc.z);
        acc.w = fmaf(wk, v.w, acc.w);
    }

    const size_t o = ((size_t)b * PS + s) * PD + col;
    float aa[4] = {acc.x, acc.y, acc.z, acc.w};
    __align__(8) __nv_bfloat16 h4[4], l4[4];
#pragma unroll
    for (int j = 0; j < 4; j++) {
        h4[j] = __float2bfloat16(aa[j]);
        l4[j] = __float2bfloat16(aa[j] - __bfloat162float(h4[j]));
    }
    *(uint2*)(f_hi + o) = *(const uint2*)h4;
    *(uint2*)(f_lo + o) = *(const uint2*)l4;
}

// ---------------------------------------------------------------------------
// kernel_launch
// Inputs: 0: x (B,S,D) f32 | 1: routes (S,K) i32 | 2: distances (S,S) f32
//         3: W_in (D,D) f32 | 4: W_out (D,D) f32 | 5: b_out (D,) f32
// ---------------------------------------------------------------------------
extern "C" void kernel_launch(void* const* d_in, const int* in_sizes, int n_in,
                              void* d_out, int out_size)
{
    const float* x      = (const float*)d_in[0];
    const int*   routes = (const int*)  d_in[1];
    const float* dist   = (const float*)d_in[2];
    const float* W_in   = (const float*)d_in[3];
    const float* W_out  = (const float*)d_in[4];
    const float* b_out  = (const float*)d_in[5];
    float*       out    = (float*)d_out;

    float *h_ptr, *w_ptr;
    __nv_bfloat16 *xh, *xl, *wih, *wil, *woh, *wol, *fh, *fl;
    cudaGetSymbolAddress((void**)&h_ptr, g_h);
    cudaGetSymbolAddress((void**)&w_ptr, g_w);
    cudaGetSymbolAddress((void**)&xh,  g_x_hi);
    cudaGetSymbolAddress((void**)&xl,  g_x_lo);
    cudaGetSymbolAddress((void**)&wih, g_wi_hi);
    cudaGetSymbolAddress((void**)&wil, g_wi_lo);
    cudaGetSymbolAddress((void**)&woh, g_wo_hi);
    cudaGetSymbolAddress((void**)&wol, g_wo_lo);
    cudaGetSymbolAddress((void**)&fh,  g_f_hi);
    cudaGetSymbolAddress((void**)&fl,  g_f_lo);

    static bool attr_set = false;
    if (!attr_set) {
        cudaFuncSetAttribute(mma_gemm_kernel<false>,
                             cudaFuncAttributeMaxDynamicSharedMemorySize, GEMM_SMEM);
        cudaFuncSetAttribute(mma_gemm_kernel<true>,
                             cudaFuncAttributeMaxDynamicSharedMemorySize, GEMM_SMEM);
        attr_set = true;
    }

    // 0) all splits in one launch
    split3_kernel<<<SPLIT_THREADS / 256, 256>>>(x, xh, xl, W_in, wih, wil, W_out, woh, wol);

    // 1) h = x @ W_in^T
    {
        dim3 grid(PD / GBN, MT / GBM);   // 8 x 32 = 256 CTAs, 2/SM
        mma_gemm_kernel<false><<<grid, 256, GEMM_SMEM>>>(xh, xl, wih, wil, h_ptr, nullptr, nullptr);
    }

    // 2) softmax weights
    softmax_kernel<<<PS, PK>>>(routes, dist, w_ptr);

    // 3) gather-fuse -> split-bf16 fused
    fuse_kernel<<<PS, 256>>>(h_ptr, routes, w_ptr, fh, fl);

    // 4) out = fused @ W_out^T + b_out + x
    {
        dim3 grid(PD / GBN, MT / GBM);
        mma_gemm_kernel<true><<<grid, 256, GEMM_SMEM>>>(fh, fl, woh, wol, out, b_out, x);
    }
}

// round 7
// speedup vs baseline: 2.6988x; 1.3704x over previous
#include <cuda_runtime.h>
#include <cuda_bf16.h>
#include <cstdint>

// Problem constants (B=2, S=2048, D=512, K=64)
#define PB 2
#define PS 2048
#define PD 512
#define PK 64
#define MT (PB * PS)   // 4096 rows total

// ---------------------------------------------------------------------------
// Scratch (device globals — no allocation allowed)
// ---------------------------------------------------------------------------
__device__ __align__(16) float         g_w[PS * PK];
__device__ __align__(16) __nv_bfloat16 g_x_bf[MT * PD];    // bf16(x)
__device__ __align__(16) __nv_bfloat16 g_h_bf[MT * PD];    // bf16(h)
__device__ __align__(16) __nv_bfloat16 g_f_bf[MT * PD];    // bf16(fused)
__device__ __align__(16) __nv_bfloat16 g_wi_hi[PD * PD];
__device__ __align__(16) __nv_bfloat16 g_wi_lo[PD * PD];
__device__ __align__(16) __nv_bfloat16 g_wo_hi[PD * PD];
__device__ __align__(16) __nv_bfloat16 g_wo_lo[PD * PD];

// ---------------------------------------------------------------------------
// PTX helpers (sm_80-level only — harness compiles via compute_103 PTX,
// which rejects all 'a'-gated tcgen05/TMEM instructions)
// ---------------------------------------------------------------------------
__device__ __forceinline__ uint32_t smem_u32(const void* p) {
    uint32_t a;
    asm("{ .reg .u64 t; cvta.to.shared.u64 t, %1; cvt.u32.u64 %0, t; }" : "=r"(a) : "l"(p));
    return a;
}

#define LDSM4(r, addr) \
    asm volatile("ldmatrix.sync.aligned.m8n8.x4.shared.b16 {%0,%1,%2,%3}, [%4];" \
                 : "=r"((r)[0]), "=r"((r)[1]), "=r"((r)[2]), "=r"((r)[3]) : "r"(addr))

#define MMA16816(d, a, b0, b1) \
    asm volatile("mma.sync.aligned.m16n8k16.row.col.f32.bf16.bf16.f32 " \
                 "{%0,%1,%2,%3}, {%4,%5,%6,%7}, {%8,%9}, {%0,%1,%2,%3};" \
                 : "+f"((d)[0]), "+f"((d)[1]), "+f"((d)[2]), "+f"((d)[3]) \
                 : "r"((a)[0]), "r"((a)[1]), "r"((a)[2]), "r"((a)[3]), "r"(b0), "r"(b1))

#define CP16(dst, src) \
    asm volatile("cp.async.cg.shared.global [%0], [%1], 16;" :: "r"(dst), "l"(src))
#define CP_COMMIT()  asm volatile("cp.async.commit_group;" ::: "memory")
#define CP_WAIT(N)   asm volatile("cp.async.wait_group %0;" :: "n"(N) : "memory")

// ---------------------------------------------------------------------------
// GEMM (NT): C[m,n] = sum_k A[m,k]*B[n,k]
//   A: plain bf16.  B ~ Bhi + Blo (split).  C = A*Bhi + A*Blo, fp32 acc.
// Tile 128x64, BK=32, 8 warps (4m x 2n, warp tile 32x32),
// 4-stage cp.async ring, one __syncthreads per K-iter, 2 CTAs/SM.
// smem row = 64B; swizzle u' = u ^ ((row>>1)&3)
// ---------------------------------------------------------------------------
#define GBM 128
#define GBN 64
#define GBK 32
#define NITER (PD / GBK)       // 16
#define STAGES 4
#define ATILEB (128 * 64)      // 8192 B
#define BTILEB (64 * 64)       // 4096 B
#define STAGEB (ATILEB + 2 * BTILEB)   // 16384 B
#define GEMM_SMEM (STAGES * STAGEB)    // 65536 B

__device__ __forceinline__ uint32_t swz(int row, int u) {
    return (uint32_t)(row * 64 + ((u ^ ((row >> 1) & 3)) * 16));
}

// OBF16: write C as bf16 to Cb (no epilogue). Else fp32 to Cf with bias+resid if EPI.
template <bool EPI, bool OBF16>
__global__ __launch_bounds__(256, 2)
void mma_gemm_kernel(const __nv_bfloat16* __restrict__ A,
                     const __nv_bfloat16* __restrict__ Bhi, const __nv_bfloat16* __restrict__ Blo,
                     float* __restrict__ Cf, __nv_bfloat16* __restrict__ Cb,
                     const float* __restrict__ bias, const float* __restrict__ resid)
{
    extern __shared__ __align__(128) char sm[];
    const uint32_t sbase = smem_u32(sm);

    const int tid  = threadIdx.x;
    const int lane = tid & 31;
    const int wid  = tid >> 5;
    const int warpM = (wid & 3) * 32;
    const int warpN = (wid >> 2) * 32;
    const int blockM = blockIdx.y * GBM;
    const int blockN = blockIdx.x * GBN;

    // cp.async mapping
    const int arow = tid >> 1;
    const int au   = (tid & 1) * 2;
    const uint32_t acd0 = swz(arow, au);
    const uint32_t acd1 = swz(arow, au + 1);
    const size_t aoff = (size_t)(blockM + arow) * PD + au * 8;
    const int brow = tid >> 2;
    const int bu   = tid & 3;
    const uint32_t bcd = swz(brow, bu);
    const size_t boff = (size_t)(blockN + brow) * PD + bu * 8;

    // ldmatrix lane mapping (fragment layout identical to proven R4-R6 kernels)
    const int mx = lane >> 3;
    const int lr = lane & 7;
    const int rA = (mx & 1) * 8 + lr;
    const int uA = mx >> 1;
    const int rB = (mx >> 1) * 8 + lr;
    const int uB = mx & 1;
    const uint32_t offA0 = (uint32_t)(warpM + rA) * 64 + ((0 + uA) ^ ((rA >> 1) & 3)) * 16;
    const uint32_t offA1 = (uint32_t)(warpM + rA) * 64 + ((2 + uA) ^ ((rA >> 1) & 3)) * 16;
    const uint32_t offB0 = (uint32_t)(warpN + rB) * 64 + ((0 + uB) ^ ((rB >> 1) & 3)) * 16;
    const uint32_t offB1 = (uint32_t)(warpN + rB) * 64 + ((2 + uB) ^ ((rB >> 1) & 3)) * 16;

    float acc[2][4][4];
#pragma unroll
    for (int mt = 0; mt < 2; mt++)
#pragma unroll
        for (int nt = 0; nt < 4; nt++)
#pragma unroll
            for (int j = 0; j < 4; j++) acc[mt][nt][j] = 0.0f;

    auto issue = [&](int chunk, int stage) {
        const int kt = chunk * GBK;
        const uint32_t sd = sbase + stage * STAGEB;
        CP16(sd + acd0, A + aoff + kt);
        CP16(sd + acd1, A + aoff + kt + 8);
        CP16(sd + ATILEB + bcd, Bhi + boff + kt);
        CP16(sd + ATILEB + BTILEB + bcd, Blo + boff + kt);
    };

    issue(0, 0); CP_COMMIT();
    issue(1, 1); CP_COMMIT();
    issue(2, 2); CP_COMMIT();

    for (int c = 0; c < NITER; c++) {
        CP_WAIT(2);
        __syncthreads();

        if (c + 3 < NITER) issue(c + 3, (c + 3) & 3);
        CP_COMMIT();

        const uint32_t sb = sbase + (c & 3) * STAGEB;

#pragma unroll
        for (int hk = 0; hk < 2; hk++) {
            const uint32_t oA = hk ? offA1 : offA0;
            const uint32_t oB = hk ? offB1 : offB0;
            uint32_t ah[2][4];
#pragma unroll
            for (int mt = 0; mt < 2; mt++)
                LDSM4(ah[mt], sb + oA + mt * 1024);
#pragma unroll
            for (int np = 0; np < 2; np++) {
                uint32_t bh[4], bl[4];
                LDSM4(bh, sb + ATILEB + oB + np * 1024);
                LDSM4(bl, sb + ATILEB + BTILEB + oB + np * 1024);
#pragma unroll
                for (int sub = 0; sub < 2; sub++) {
                    const int nt = np * 2 + sub;
                    const uint32_t b0h = bh[sub * 2], b1h = bh[sub * 2 + 1];
                    const uint32_t b0l = bl[sub * 2], b1l = bl[sub * 2 + 1];
#pragma unroll
                    for (int mt = 0; mt < 2; mt++) {
                        MMA16816(acc[mt][nt], ah[mt], b0h, b1h);
                        MMA16816(acc[mt][nt], ah[mt], b0l, b1l);
                    }
                }
            }
        }
        __syncthreads();
    }

    // --- epilogue ---
    const int g  = lane >> 2;
    const int tg = lane & 3;
#pragma unroll
    for (int mt = 0; mt < 2; mt++) {
#pragma unroll
        for (int nt = 0; nt < 4; nt++) {
            const int row = blockM + warpM + mt * 16 + g;
            const int col = blockN + warpN + nt * 8 + tg * 2;
            const size_t o0 = (size_t)row * PD + col;
            const size_t o1 = (size_t)(row + 8) * PD + col;
            if (OBF16) {
                *(__nv_bfloat162*)&Cb[o0] = __floats2bfloat162_rn(acc[mt][nt][0], acc[mt][nt][1]);
                *(__nv_bfloat162*)&Cb[o1] = __floats2bfloat162_rn(acc[mt][nt][2], acc[mt][nt][3]);
            } else {
                float2 v0 = make_float2(acc[mt][nt][0], acc[mt][nt][1]);
                float2 v1 = make_float2(acc[mt][nt][2], acc[mt][nt][3]);
                if (EPI) {
                    const float2 bb = *(const float2*)&bias[col];
                    const float2 x0 = *(const float2*)&resid[o0];
                    const float2 x1 = *(const float2*)&resid[o1];
                    v0.x += bb.x + x0.x; v0.y += bb.y + x0.y;
                    v1.x += bb.x + x1.x; v1.y += bb.y + x1.y;
                }
                *(float2*)&Cf[o0] = v0;
                *(float2*)&Cf[o1] = v1;
            }
        }
    }
}

// ---------------------------------------------------------------------------
// Prep: x -> bf16; W_in, W_out -> (hi, lo) split. One launch.
// ---------------------------------------------------------------------------
#define NX (MT * PD)      // 2097152
#define NW (PD * PD)      // 262144
#define PREP_THREADS ((NX + 2 * NW) / 4)

__device__ __forceinline__ void split4(const float* src, __nv_bfloat16* hi,
                                       __nv_bfloat16* lo, int i)
{
    const float4 v = *(const float4*)(src + i);
    float vv[4] = {v.x, v.y, v.z, v.w};
    __align__(8) __nv_bfloat16 h4[4], l4[4];
#pragma unroll
    for (int j = 0; j < 4; j++) {
        h4[j] = __float2bfloat16(vv[j]);
        l4[j] = __float2bfloat16(vv[j] - __bfloat162float(h4[j]));
    }
    *(uint2*)(hi + i) = *(const uint2*)h4;
    *(uint2*)(lo + i) = *(const uint2*)l4;
}

__global__ __launch_bounds__(256)
void prep_kernel(const float* __restrict__ x,  __nv_bfloat16* __restrict__ xb,
                 const float* __restrict__ Wi, __nv_bfloat16* __restrict__ wih, __nv_bfloat16* __restrict__ wil,
                 const float* __restrict__ Wo, __nv_bfloat16* __restrict__ woh, __nv_bfloat16* __restrict__ wol)
{
    const int t = blockIdx.x * blockDim.x + threadIdx.x;
    const int i = t * 4;
    if (i < NX) {
        const float4 v = *(const float4*)(x + i);
        __align__(8) __nv_bfloat16 h4[4];
        h4[0] = __float2bfloat16(v.x);
        h4[1] = __float2bfloat16(v.y);
        h4[2] = __float2bfloat16(v.z);
        h4[3] = __float2bfloat16(v.w);
        *(uint2*)(xb + i) = *(const uint2*)h4;
    } else if (i < NX + NW) {
        split4(Wi, wih, wil, i - NX);
    } else {
        split4(Wo, woh, wol, i - NX - NW);
    }
}

// ---------------------------------------------------------------------------
// Softmax: w[s,k] = softmax_k(-distances[s, routes[s,k]])
// ---------------------------------------------------------------------------
__global__ __launch_bounds__(PK)
void softmax_kernel(const int* __restrict__ routes, const float* __restrict__ dist,
                    float* __restrict__ w)
{
    const int s = blockIdx.x;
    const int t = threadIdx.x;
    __shared__ float red[PK];

    const int r = routes[s * PK + t];
    const float v = -dist[(size_t)s * PS + r];

    red[t] = v;
    __syncthreads();
#pragma unroll
    for (int off = PK / 2; off > 0; off >>= 1) {
        if (t < off) red[t] = fmaxf(red[t], red[t + off]);
        __syncthreads();
    }
    const float m = red[0];
    __syncthreads();

    const float e = __expf(v - m);
    red[t] = e;
    __syncthreads();
#pragma unroll
    for (int off = PK / 2; off > 0; off >>= 1) {
        if (t < off) red[t] += red[t + off];
        __syncthreads();
    }
    w[s * PK + t] = e / red[0];
}

// ---------------------------------------------------------------------------
// Gather-fuse (bf16 h): fused[b,s,:] = sum_k w[s,k] * h[b, routes[s,k], :]
// Block = 256 threads = 2 s x 2 b x 64 col-threads (8 cols each, one 16B load/k).
// fp32 accumulate, emits plain bf16 fused.
// ---------------------------------------------------------------------------
__global__ __launch_bounds__(256)
void fuse_kernel(const __nv_bfloat16* __restrict__ h, const int* __restrict__ routes,
                 const float* __restrict__ w, __nv_bfloat16* __restrict__ f)
{
    const int tid = threadIdx.x;
    const int sl  = tid >> 7;                 // local s (0/1)
    const int b   = (tid >> 6) & 1;
    const int t   = tid & 63;
    const int s   = blockIdx.x * 2 + sl;

    __shared__ float ws[2][PK];
    __shared__ int   rs[2][PK];
    if (tid < 128) {
        const int ls = tid >> 6, kk = tid & 63;
        const int sg = blockIdx.x * 2 + ls;
        ws[ls][kk] = w[sg * PK + kk];
        rs[ls][kk] = routes[sg * PK + kk];
    }
    __syncthreads();

    const __nv_bfloat16* hb = h + (size_t)b * PS * PD;
    const int col = t * 8;

    float acc[8];
#pragma unroll
    for (int j = 0; j < 8; j++) acc[j] = 0.0f;

#pragma unroll 4
    for (int k = 0; k < PK; k++) {
        const float wk = ws[sl][k];
        const uint4 v = *(const uint4*)&hb[(size_t)rs[sl][k] * PD + col];
        const __nv_bfloat162* p = (const __nv_bfloat162*)&v;
#pragma unroll
        for (int j = 0; j < 4; j++) {
            const float2 f2 = __bfloat1622float2(p[j]);
            acc[2 * j]     = fmaf(wk, f2.x, acc[2 * j]);
            acc[2 * j + 1] = fmaf(wk, f2.y, acc[2 * j + 1]);
        }
    }

    __align__(16) __nv_bfloat162 o[4];
#pragma unroll
    for (int j = 0; j < 4; j++)
        o[j] = __floats2bfloat162_rn(acc[2 * j], acc[2 * j + 1]);
    *(uint4*)&f[((size_t)b * PS + s) * PD + col] = *(const uint4*)o;
}

// ---------------------------------------------------------------------------
// kernel_launch
// Inputs: 0: x (B,S,D) f32 | 1: routes (S,K) i32 | 2: distances (S,S) f32
//         3: W_in (D,D) f32 | 4: W_out (D,D) f32 | 5: b_out (D,) f32
// ---------------------------------------------------------------------------
extern "C" void kernel_launch(void* const* d_in, const int* in_sizes, int n_in,
                              void* d_out, int out_size)
{
    const float* x      = (const float*)d_in[0];
    const int*   routes = (const int*)  d_in[1];
    const float* dist   = (const float*)d_in[2];
    const float* W_in   = (const float*)d_in[3];
    const float* W_out  = (const float*)d_in[4];
    const float* b_out  = (const float*)d_in[5];
    float*       out    = (float*)d_out;

    float* w_ptr;
    __nv_bfloat16 *xb, *hb, *fb, *wih, *wil, *woh, *wol;
    cudaGetSymbolAddress((void**)&w_ptr, g_w);
    cudaGetSymbolAddress((void**)&xb,  g_x_bf);
    cudaGetSymbolAddress((void**)&hb,  g_h_bf);
    cudaGetSymbolAddress((void**)&fb,  g_f_bf);
    cudaGetSymbolAddress((void**)&wih, g_wi_hi);
    cudaGetSymbolAddress((void**)&wil, g_wi_lo);
    cudaGetSymbolAddress((void**)&woh, g_wo_hi);
    cudaGetSymbolAddress((void**)&wol, g_wo_lo);

    static bool attr_set = false;
    if (!attr_set) {
        cudaFuncSetAttribute((const void*)mma_gemm_kernel<false, true>,
                             cudaFuncAttributeMaxDynamicSharedMemorySize, GEMM_SMEM);
        cudaFuncSetAttribute((const void*)mma_gemm_kernel<true, false>,
                             cudaFuncAttributeMaxDynamicSharedMemorySize, GEMM_SMEM);
        attr_set = true;
    }

    // 0) prep: x->bf16, W splits
    prep_kernel<<<PREP_THREADS / 256, 256>>>(x, xb, W_in, wih, wil, W_out, woh, wol);

    // 1) h = x @ W_in^T  (bf16 out)
    {
        dim3 grid(PD / GBN, MT / GBM);   // 8 x 32 = 256 CTAs, 2/SM
        mma_gemm_kernel<false, true><<<grid, 256, GEMM_SMEM>>>(xb, wih, wil, nullptr, hb, nullptr, nullptr);
    }

    // 2) softmax weights
    softmax_kernel<<<PS, PK>>>(routes, dist, w_ptr);

    // 3) gather-fuse -> bf16 fused
    fuse_kernel<<<PS / 2, 256>>>(hb, routes, w_ptr, fb);

    // 4) out = fused @ W_out^T + b_out + x
    {
        dim3 grid(PD / GBN, MT / GBM);
        mma_gemm_kernel<true, false><<<grid, 256, GEMM_SMEM>>>(fb, woh, wol, out, nullptr, b_out, x);
    }
}